// round 13
// baseline (speedup 1.0000x reference)
#include <cuda_runtime.h>
#include <cuda_bf16.h>
#include <cuda_fp16.h>
#include <math.h>

#define NN 20000
#define HID 128
#define GBM 313         // GEMM blocks for 20000 rows @64/tile
#define SZB 40          // blocks to zero s1|s2 (2*NN/4 float4s)

// ---------------- single scratch buffer ----------------
#define OFF_H     0
#define OFF_M     2560000
#define OFF_SKIP  5120000
#define OFF_AGG0  7680000    // agg0 | s1a | s2a
#define OFF_AGG1  10280000   // agg1 | s1b | s2b
#define OFF_DEG   12880000   // deg1 | deg2 (float)
#define OFF_AGGH  12920000   // fp16 mirror of relu(agg)
#define OFF_WC1   14200000
#define OFF_WC2   14216384
#define OFF_WPK   14232768   // packed bf16 hi/lo weights
#define OFF_CNT   14298304   // int cntcol[NN]
#define OFF_INDPTR 14318304  // int indptr[NN+1]
#define OFF_WOFF  14338308   // int woff[NN]
#define OFF_PERM  14358308   // int perm[<=121000]
#define SCRATCH_F 14479308
__device__ float g_scratch[SCRATCH_F];

// ---------------- helpers ----------------
__device__ __forceinline__ float warp_red(float s) {
#pragma unroll
    for (int off = 16; off; off >>= 1) s += __shfl_xor_sync(0xffffffffu, s, off);
    return s;
}

__device__ __forceinline__ float4 relu4(float4 v) {
    return make_float4(fmaxf(v.x, 0.f), fmaxf(v.y, 0.f), fmaxf(v.z, 0.f), fmaxf(v.w, 0.f));
}

__device__ __forceinline__ float4 h4_to_f4(uint2 u) {
    __half2 a = *reinterpret_cast<__half2*>(&u.x);
    __half2 b = *reinterpret_cast<__half2*>(&u.y);
    float2 fa = __half22float2(a);
    float2 fb = __half22float2(b);
    return make_float4(fa.x, fa.y, fb.x, fb.y);
}

__device__ __forceinline__ void split_bf16(float f, unsigned short& h, unsigned short& l) {
    __nv_bfloat16 bh = __float2bfloat16_rn(f);
    float r = f - __bfloat162float(bh);
    __nv_bfloat16 bl = __float2bfloat16_rn(r);
    h = __bfloat16_as_ushort(bh);
    l = __bfloat16_as_ushort(bl);
}
__device__ __forceinline__ unsigned pack2(unsigned short lo_even, unsigned short hi_odd) {
    return ((unsigned)hi_odd << 16) | (unsigned)lo_even;
}

// ---------------- pre1: tiny fp32 GEMMs (blocks 0..15) + zero deg/cntcol tail ----------------
__global__ void pre1(const float* __restrict__ A,
                     const float* __restrict__ B1, const float* __restrict__ B2,
                     float* __restrict__ C1, float* __restrict__ C2,
                     float4* __restrict__ deg4, int4* __restrict__ cnt4) {
    int tid = threadIdx.x;
    if (blockIdx.x >= 16) {
        int i = (blockIdx.x - 16) * 256 + tid;
        if (i < 2 * NN / 4) deg4[i] = make_float4(0.f, 0.f, 0.f, 0.f);
        else if (i < 2 * NN / 4 + NN / 4) cnt4[i - 2 * NN / 4] = make_int4(0, 0, 0, 0);
        return;
    }
    int mat = blockIdx.x >> 3;
    int colBase = (blockIdx.x & 7) * 16;
    const float* B = mat ? B2 : B1;
    float* C = mat ? C2 : C1;
    __shared__ float As[16][129];
    __shared__ float Bs[16][16];
    int r = tid & 127;
    int cg = tid >> 7;
    float acc[8];
#pragma unroll
    for (int j = 0; j < 8; j++) acc[j] = 0.0f;
    for (int k0 = 0; k0 < 128; k0 += 16) {
        for (int i = tid; i < 128 * 16; i += 256) {
            int rr = i >> 4, kk = i & 15;
            As[kk][rr] = A[rr * 128 + k0 + kk];
        }
        {
            int kk = tid >> 4, cc = tid & 15;
            Bs[kk][cc] = B[(k0 + kk) * 128 + colBase + cc];
        }
        __syncthreads();
#pragma unroll
        for (int kk = 0; kk < 16; kk++) {
            float a = As[kk][r];
#pragma unroll
            for (int j = 0; j < 8; j++)
                acc[j] = fmaf(a, Bs[kk][cg * 8 + j], acc[j]);
        }
        __syncthreads();
    }
#pragma unroll
    for (int j = 0; j < 8; j++)
        C[r * 128 + colBase + cg * 8 + j] = acc[j];
}

// ---------------- pre2: prepack (blocks 0..127) + degree counts + col histogram ----------------
__global__ void pre2(const float* __restrict__ inW, const float* __restrict__ wc1,
                     const float* __restrict__ wc2, const float* __restrict__ convW1,
                     unsigned* __restrict__ wpk,
                     const int* __restrict__ row1, const int* __restrict__ col1, int E1,
                     const int* __restrict__ row2, int E2,
                     float* __restrict__ deg, int* __restrict__ cntcol) {
    int tid = threadIdx.x;
    if (blockIdx.x >= 128) {
        int e = (blockIdx.x - 128) * 256 + tid;
        if (e >= E1 + E2) return;
        int key = (e < E1) ? row1[e] : (NN + row2[e - E1]);
        unsigned m = __match_any_sync(__activemask(), key);
        if ((tid & 31) == (__ffs(m) - 1)) atomicAdd(&deg[key], (float)__popc(m));
        if (e < E1) atomicAdd(&cntcol[col1[e]], 1);
        return;
    }
    int idx = blockIdx.x * 256 + tid;
    int mat = idx >> 13;
    int rem = idx & 8191;
    int c = rem >> 10;
    int p = (rem >> 7) & 7;
    int n = rem & 127;
    const float* W = (mat == 0) ? inW : (mat == 1) ? wc1 : (mat == 2) ? wc2 : convW1;
    int k0 = c * 16 + 2 * p;
    float we = W[k0 * 128 + n];
    float wo = W[(k0 + 1) * 128 + n];
    unsigned short he, le, ho, lo_;
    split_bf16(we, he, le);
    split_bf16(wo, ho, lo_);
    wpk[mat * 16384 + rem] = pack2(he, ho);
    wpk[mat * 16384 + 8192 + rem] = pack2(le, lo_);
}

// ---------------- prefix scan of cntcol -> indptr, woff (1 block) ----------------
__global__ __launch_bounds__(1024) void prefix_k(const int* __restrict__ cnt,
                                                 int* __restrict__ indptr,
                                                 int* __restrict__ woff) {
    __shared__ int ps[1024];
    const int CH = (NN + 1023) / 1024;   // 20
    int t = threadIdx.x;
    int base = t * CH;
    int loc[CH];
    int s = 0;
#pragma unroll
    for (int j = 0; j < CH; j++) {
        int v = (base + j < NN) ? cnt[base + j] : 0;
        loc[j] = s;
        s += v;
    }
    ps[t] = s;
    __syncthreads();
    for (int off = 1; off < 1024; off <<= 1) {
        int v = (t >= off) ? ps[t - off] : 0;
        __syncthreads();
        ps[t] += v;
        __syncthreads();
    }
    int excl = (t == 0) ? 0 : ps[t - 1];
#pragma unroll
    for (int j = 0; j < CH; j++) {
        int idx = base + j;
        if (idx < NN) {
            int val = excl + loc[j];
            indptr[idx] = val;
            woff[idx] = val;
        }
    }
    if (t == 1023) indptr[NN] = ps[1023];
}

// ---------------- split-BF16 tensor GEMM, M=64 tile + tails ----------------
// MODE 3: triple GEMM; tail: zero s-region (SZB blocks) then perm-build.
// MODE 2: fused h-update GEMM; tail: zero s-region only.
#define KCH 16
#define SPA 72
#define SPW 136
template<int MODE>
__global__ __launch_bounds__(256, 2) void gemm_k(
    const float* A, const float* __restrict__ A2, const unsigned* __restrict__ wpk,
    float* __restrict__ C, float* __restrict__ C2, float* __restrict__ C3,
    const float* __restrict__ agg, const float* __restrict__ skipb,
    const float* __restrict__ s1, const float* __restrict__ s2,
    const float* __restrict__ deg1, const float* __restrict__ deg2,
    float* hout,
    float4* __restrict__ sZero4,
    int* __restrict__ woff, int* __restrict__ perm,
    const int* __restrict__ prow, const int* __restrict__ pcol, int E1p,
    int gemmBlocks, int N) {
    const int tid = threadIdx.x;

    if ((int)blockIdx.x >= gemmBlocks) {
        int i = (int)blockIdx.x - gemmBlocks;
        if (i < SZB) {
            int idx = i * 256 + tid;
            if (idx < 2 * NN / 4) sZero4[idx] = make_float4(0.f, 0.f, 0.f, 0.f);
        } else if (MODE == 3) {
            int e = (i - SZB) * 256 + tid;
            if (e < E1p) {
                int c = pcol[e];
                int pos = atomicAdd(&woff[c], 1);
                perm[pos] = prow[e];
            }
        }
        return;
    }

    __shared__ unsigned As_hi[8 * SPA], As_lo[8 * SPA];
    __shared__ unsigned Wv_hi[8 * SPW], Wv_lo[8 * SPW];
    __shared__ float cg1[64], cg2[64], cid[64];

    const int lane = tid & 31;
    const int warp = tid >> 5;
    const int g = lane >> 2;
    const int t = lane & 3;
    const int wm = warp & 3;
    const int wn = warp >> 2;
    const int mbase = wm * 16;
    const int nbase = wn * 64;

    const float* Ap = A;
    float* Cp = C;
    int mat, rb = blockIdx.x;
    if (MODE == 3) {
        if (rb < GBM) { mat = 0; }
        else if (rb < 2 * GBM) { mat = 1; Ap = A2; Cp = C2; rb -= GBM; }
        else { mat = 2; Cp = C3; rb -= 2 * GBM; }
    } else {
        mat = 3;
    }
    const int rowBase = rb * 64;
    const unsigned* Wh = wpk + mat * 16384;
    const unsigned* Wl = Wh + 8192;

    if (MODE == 2) {
        if (tid < 64) {
            int r = rowBase + tid;
            float G1 = 0.f, G2 = 0.f, ID = 1.f;
            if (r < N) {
                G1 = tanhf(s1[r] / (deg1[r] + 1e-10f));
                G2 = tanhf(s2[r] / (deg2[r] + 1e-10f));
                ID = 1.0f / (1.0f + G1 + G2);
            }
            cg1[tid] = G1; cg2[tid] = G2; cid[tid] = ID;
        }
        __syncthreads();
    }

    float acc[8][4];
#pragma unroll
    for (int n = 0; n < 8; n++)
#pragma unroll
        for (int j = 0; j < 4; j++) acc[n][j] = 0.0f;

    float4 pa;
    uint4 pwh, pwl;
    const int wp = tid >> 5;
    const int wnc = (tid & 31) * 4;

    auto loadA = [&](int k0) {
        int r = tid >> 2;
        int kq = (tid & 3) * 4;
        float4 v = make_float4(0.f, 0.f, 0.f, 0.f);
        if (rowBase + r < N) {
            size_t off = (size_t)(rowBase + r) * HID + k0 + kq;
            if (MODE == 2) {
                float4 h4 = *reinterpret_cast<const float4*>(&Ap[off]);
                float4 a4 = relu4(*reinterpret_cast<const float4*>(&agg[off]));
                float4 k4 = *reinterpret_cast<const float4*>(&skipb[off]);
                float G1 = cg1[r], G2 = cg2[r], ID = cid[r];
                v.x = (h4.x + G1 * a4.x + G2 * k4.x) * ID;
                v.y = (h4.y + G1 * a4.y + G2 * k4.y) * ID;
                v.z = (h4.z + G1 * a4.z + G2 * k4.z) * ID;
                v.w = (h4.w + G1 * a4.w + G2 * k4.w) * ID;
                *reinterpret_cast<float4*>(&hout[off]) = v;
            } else {
                v = *reinterpret_cast<const float4*>(&Ap[off]);
            }
        }
        pa = v;
    };
    auto loadW = [&](int c) {
        pwh = *reinterpret_cast<const uint4*>(&Wh[c * 1024 + wp * 128 + wnc]);
        pwl = *reinterpret_cast<const uint4*>(&Wl[c * 1024 + wp * 128 + wnc]);
    };

    loadA(0); loadW(0);

    for (int c = 0; c < 8; c++) {
        {
            int r = tid >> 2;
            int p0 = (tid & 3) * 2;
            float f[4] = {pa.x, pa.y, pa.z, pa.w};
            unsigned short h[4], l[4];
#pragma unroll
            for (int j = 0; j < 4; j++) split_bf16(f[j], h[j], l[j]);
            As_hi[p0 * SPA + r] = pack2(h[0], h[1]);
            As_lo[p0 * SPA + r] = pack2(l[0], l[1]);
            As_hi[(p0 + 1) * SPA + r] = pack2(h[2], h[3]);
            As_lo[(p0 + 1) * SPA + r] = pack2(l[2], l[3]);
        }
        *reinterpret_cast<uint4*>(&Wv_hi[wp * SPW + wnc]) = pwh;
        *reinterpret_cast<uint4*>(&Wv_lo[wp * SPW + wnc]) = pwl;
        __syncthreads();

        if (c + 1 < 8) { loadA((c + 1) * KCH); loadW(c + 1); }

        unsigned ah[4], al[4];
        ah[0] = As_hi[t * SPA + mbase + g];
        ah[1] = As_hi[t * SPA + mbase + g + 8];
        ah[2] = As_hi[(t + 4) * SPA + mbase + g];
        ah[3] = As_hi[(t + 4) * SPA + mbase + g + 8];
        al[0] = As_lo[t * SPA + mbase + g];
        al[1] = As_lo[t * SPA + mbase + g + 8];
        al[2] = As_lo[(t + 4) * SPA + mbase + g];
        al[3] = As_lo[(t + 4) * SPA + mbase + g + 8];
#pragma unroll
        for (int j = 0; j < 8; j++) {
            int n = nbase + j * 8 + g;
            unsigned bh0 = Wv_hi[t * SPW + n];
            unsigned bh1 = Wv_hi[(t + 4) * SPW + n];
            unsigned bl0 = Wv_lo[t * SPW + n];
            unsigned bl1 = Wv_lo[(t + 4) * SPW + n];
            asm volatile("mma.sync.aligned.m16n8k16.row.col.f32.bf16.bf16.f32 "
                         "{%0,%1,%2,%3}, {%4,%5,%6,%7}, {%8,%9}, {%0,%1,%2,%3};"
                         : "+f"(acc[j][0]), "+f"(acc[j][1]), "+f"(acc[j][2]), "+f"(acc[j][3])
                         : "r"(ah[0]), "r"(ah[1]), "r"(ah[2]), "r"(ah[3]), "r"(bh0), "r"(bh1));
            asm volatile("mma.sync.aligned.m16n8k16.row.col.f32.bf16.bf16.f32 "
                         "{%0,%1,%2,%3}, {%4,%5,%6,%7}, {%8,%9}, {%0,%1,%2,%3};"
                         : "+f"(acc[j][0]), "+f"(acc[j][1]), "+f"(acc[j][2]), "+f"(acc[j][3])
                         : "r"(ah[0]), "r"(ah[1]), "r"(ah[2]), "r"(ah[3]), "r"(bl0), "r"(bl1));
            asm volatile("mma.sync.aligned.m16n8k16.row.col.f32.bf16.bf16.f32 "
                         "{%0,%1,%2,%3}, {%4,%5,%6,%7}, {%8,%9}, {%0,%1,%2,%3};"
                         : "+f"(acc[j][0]), "+f"(acc[j][1]), "+f"(acc[j][2]), "+f"(acc[j][3])
                         : "r"(al[0]), "r"(al[1]), "r"(al[2]), "r"(al[3]), "r"(bh0), "r"(bh1));
        }
        __syncthreads();
    }

    int r0 = rowBase + mbase + g;
    int r1 = r0 + 8;
    if (r0 < N) {
#pragma unroll
        for (int j = 0; j < 8; j++)
            *reinterpret_cast<float2*>(&Cp[(size_t)r0 * HID + nbase + j * 8 + 2 * t]) =
                make_float2(acc[j][0], acc[j][1]);
    }
    if (r1 < N) {
#pragma unroll
        for (int j = 0; j < 8; j++)
            *reinterpret_cast<float2*>(&Cp[(size_t)r1 * HID + nbase + j * 8 + 2 * t]) =
                make_float2(acc[j][2], acc[j][3]);
    }
}

// ---------------- sorted scatter: warp per node, register accumulation ----------------
// agg[v] = bias + sum_{e: col=v} m[row_e]; aggh[v] = fp16(relu(agg[v]))
__global__ void scatter_sorted(const float* __restrict__ m, const int* __restrict__ indptr,
                               const int* __restrict__ perm, const float4* __restrict__ bias4,
                               float* __restrict__ agg, uint2* __restrict__ aggh) {
    int w = (blockIdx.x * blockDim.x + threadIdx.x) >> 5;
    if (w >= NN) return;
    int lane = threadIdx.x & 31;
    int beg = indptr[w], end = indptr[w + 1];
    float4 acc = bias4[lane];
    int e = beg;
    for (; e + 4 <= end; e += 4) {
        int r0 = perm[e], r1 = perm[e + 1], r2 = perm[e + 2], r3 = perm[e + 3];
        float4 v0 = *reinterpret_cast<const float4*>(&m[(size_t)r0 * HID + lane * 4]);
        float4 v1 = *reinterpret_cast<const float4*>(&m[(size_t)r1 * HID + lane * 4]);
        float4 v2 = *reinterpret_cast<const float4*>(&m[(size_t)r2 * HID + lane * 4]);
        float4 v3 = *reinterpret_cast<const float4*>(&m[(size_t)r3 * HID + lane * 4]);
        acc.x += v0.x + v1.x + v2.x + v3.x;
        acc.y += v0.y + v1.y + v2.y + v3.y;
        acc.z += v0.z + v1.z + v2.z + v3.z;
        acc.w += v0.w + v1.w + v2.w + v3.w;
    }
    for (; e < end; e++) {
        int r = perm[e];
        float4 v = *reinterpret_cast<const float4*>(&m[(size_t)r * HID + lane * 4]);
        acc.x += v.x; acc.y += v.y; acc.z += v.z; acc.w += v.w;
    }
    *reinterpret_cast<float4*>(&agg[(size_t)w * HID + lane * 4]) = acc;
    __half2 a = __float22half2_rn(make_float2(fmaxf(acc.x, 0.f), fmaxf(acc.y, 0.f)));
    __half2 b = __float22half2_rn(make_float2(fmaxf(acc.z, 0.f), fmaxf(acc.w, 0.f)));
    uint2 o;
    o.x = *reinterpret_cast<unsigned*>(&a);
    o.y = *reinterpret_cast<unsigned*>(&b);
    aggh[(size_t)w * 32 + lane] = o;
}

// ---------------- fused gamma (1-hop warp/edge; 2-hop chunked, MLP=4) ----------------
#define G2_CHUNK 64
__global__ void gamma_both(const uint2* __restrict__ aggh,
                           const int* __restrict__ row1, const int* __restrict__ col1,
                           float* __restrict__ s1, int E1, int blocks1,
                           const int* __restrict__ row2, const int* __restrict__ col2,
                           float* __restrict__ s2, int E2) {
    int lane = threadIdx.x & 31;
    if (blockIdx.x < blocks1) {
        int w = (blockIdx.x * blockDim.x + threadIdx.x) >> 5;
        if (w >= E1) return;
        int r = row1[w];
        int c = col1[w];
        float4 a = h4_to_f4(aggh[(size_t)r * 32 + lane]);
        float4 b = h4_to_f4(aggh[(size_t)c * 32 + lane]);
        float dx = a.x - b.x, dy = a.y - b.y, dz = a.z - b.z, dw = a.w - b.w;
        float s = warp_red(fmaf(dx, dx, fmaf(dy, dy, fmaf(dz, dz, dw * dw))));
        if (lane == 0) atomicAdd(&s1[r], s);
    } else {
        int w = (int)((((size_t)(blockIdx.x - blocks1) * blockDim.x) + threadIdx.x) >> 5);
        int base = w * G2_CHUNK;
        if (base >= E2) return;
        int end = min(base + G2_CHUNK, E2);
        int curR = row2[base];
        float4 ar = h4_to_f4(aggh[(size_t)curR * 32 + lane]);
        float acc = 0.0f;
        int e = base;
        while (e < end) {
            int n4 = end - e;
            if (n4 > 4) n4 = 4;
            int r4[4];
            uint2 c4[4];
#pragma unroll
            for (int j = 0; j < 4; j++) {
                if (j < n4) {
                    r4[j] = row2[e + j];
                    c4[j] = aggh[(size_t)col2[e + j] * 32 + lane];
                }
            }
#pragma unroll
            for (int j = 0; j < 4; j++) {
                if (j < n4) {
                    if (r4[j] != curR) {
                        float s = warp_red(acc);
                        if (lane == 0) atomicAdd(&s2[curR], s);
                        acc = 0.0f;
                        curR = r4[j];
                        ar = h4_to_f4(aggh[(size_t)curR * 32 + lane]);
                    }
                    float4 ac = h4_to_f4(c4[j]);
                    float dx = ar.x - ac.x, dy = ar.y - ac.y;
                    float dz = ar.z - ac.z, dw = ar.w - ac.w;
                    acc += fmaf(dx, dx, fmaf(dy, dy, fmaf(dz, dz, dw * dw)));
                }
            }
            e += n4;
        }
        float s = warp_red(acc);
        if (lane == 0) atomicAdd(&s2[curR], s);
    }
}

// ---------------- final GEMM with fused layer-2 h-update ----------------
#define ORPB 16
__global__ __launch_bounds__(640) void gemm_out_upd(
    const float* __restrict__ h, const float* __restrict__ agg, const float* __restrict__ skip,
    const float* __restrict__ s1, const float* __restrict__ s2,
    const float* __restrict__ deg1, const float* __restrict__ deg2,
    const float* __restrict__ W, const float* __restrict__ bias,
    float* __restrict__ C, int N) {
    __shared__ float Ws[HID * 41];
    __shared__ float bs[40];
    __shared__ float As[ORPB][HID];
    __shared__ float cg1[ORPB], cg2[ORPB], cid[ORPB];
    int tid = threadIdx.y * 40 + threadIdx.x;
    int rowBase = blockIdx.x * ORPB;

    for (int i = tid; i < HID * 40; i += 640) {
        int k = i / 40, n = i % 40;
        Ws[k * 41 + n] = W[i];
    }
    if (tid < 40) bs[tid] = bias[tid];
    if (tid < ORPB) {
        int r = rowBase + tid;
        float g1 = 0.f, g2 = 0.f, invd = 1.f;
        if (r < N) {
            g1 = tanhf(s1[r] / (deg1[r] + 1e-10f));
            g2 = tanhf(s2[r] / (deg2[r] + 1e-10f));
            invd = 1.0f / (1.0f + g1 + g2);
        }
        cg1[tid] = g1; cg2[tid] = g2; cid[tid] = invd;
    }
    __syncthreads();

    for (int i = tid; i < ORPB * HID; i += 640) {
        int rr = i >> 7, kk = i & (HID - 1);
        int r = rowBase + rr;
        float v = 0.0f;
        if (r < N) {
            size_t off = (size_t)r * HID + kk;
            v = (h[off] + cg1[rr] * fmaxf(agg[off], 0.f) + cg2[rr] * skip[off]) * cid[rr];
        }
        As[rr][kk] = v;
    }
    __syncthreads();

    int row = rowBase + threadIdx.y;
    if (row >= N) return;
    float acc = bs[threadIdx.x];
#pragma unroll
    for (int k = 0; k < HID; k++) acc = fmaf(As[threadIdx.y][k], Ws[k * 41 + threadIdx.x], acc);
    C[(size_t)row * 40 + threadIdx.x] = acc;
}

// ---------------- launcher ----------------
extern "C" void kernel_launch(void* const* d_in, const int* in_sizes, int n_in,
                              void* d_out, int out_size) {
    const float* x       = (const float*)d_in[0];
    const float* x0      = (const float*)d_in[1];
    const int*   ei      = (const int*)d_in[2];
    const int*   ei2     = (const int*)d_in[3];
    const float* in_W    = (const float*)d_in[4];
    const float* skip_W  = (const float*)d_in[5];
    const float* conv_W  = (const float*)d_in[6];
    const float* conv_b  = (const float*)d_in[7];
    const float* fc_W    = (const float*)d_in[8];
    const float* fc_b    = (const float*)d_in[9];
    float* out = (float*)d_out;

    const int E1 = in_sizes[2] / 2;
    const int E2 = in_sizes[3] / 2;
    const int* row1 = ei;
    const int* col1 = ei + E1;
    const int* row2 = ei2;
    const int* col2 = ei2 + E2;

    float* base;
    cudaGetSymbolAddress((void**)&base, g_scratch);
    float* h    = base + OFF_H;
    float* m    = base + OFF_M;
    float* skip = base + OFF_SKIP;
    float* agg0 = base + OFF_AGG0;
    float* s1a  = agg0 + NN * HID;
    float* s2a  = s1a + NN;
    float* agg1 = base + OFF_AGG1;
    float* s1b  = agg1 + NN * HID;
    float* s2b  = s1b + NN;
    float* deg1 = base + OFF_DEG;
    float* deg2 = deg1 + NN;
    uint2* aggh = (uint2*)(base + OFF_AGGH);
    float* wc1  = base + OFF_WC1;
    float* wc2  = base + OFF_WC2;
    unsigned* wpk = (unsigned*)(base + OFF_WPK);
    int* cntcol = (int*)(base + OFF_CNT);
    int* indptr = (int*)(base + OFF_INDPTR);
    int* woff   = (int*)(base + OFF_WOFF);
    int* perm   = (int*)(base + OFF_PERM);

    const int NTH = 256;
    const int zeroB   = (2 * NN / 4 + NN / 4 + NTH - 1) / NTH;   // deg + cntcol
    const int blocks1 = (int)(((size_t)E1 * 32 + NTH - 1) / NTH);
    const int warps2  = (E2 + G2_CHUNK - 1) / G2_CHUNK;
    const int blocks2 = (warps2 * 32 + NTH - 1) / NTH;
    const int countB  = (E1 + E2 + NTH - 1) / NTH;
    const int permB   = (E1 + NTH - 1) / NTH;
    const int scatB   = (NN * 32 + NTH - 1) / NTH;

    // pre1: Wc1/Wc2 tiny GEMMs + zero deg/cntcol
    pre1<<<16 + zeroB, NTH>>>(in_W, skip_W, conv_W, wc1, wc2,
                              (float4*)deg1, (int4*)cntcol);
    // pre2: weight prepack + row-degree counts + col histogram
    pre2<<<128 + countB, NTH>>>(in_W, wc1, wc2, conv_W + (size_t)HID * HID, wpk,
                                row1, col1, E1, row2, E2, deg1, cntcol);
    // prefix scan -> indptr, woff
    prefix_k<<<1, 1024>>>(cntcol, indptr, woff);

    // triple GEMM (h = x@in_W ; skip = x0@Wc1 ; m = x@Wc2) + zero s1a|s2a + perm build
    gemm_k<3><<<3 * GBM + SZB + permB, NTH>>>(x, x0, wpk, h, skip, m,
                                              nullptr, nullptr, nullptr, nullptr,
                                              nullptr, nullptr, nullptr,
                                              (float4*)s1a, woff, perm, row1, col1, E1,
                                              3 * GBM, NN);

    // ---- layer 0 ----
    scatter_sorted<<<scatB, NTH>>>(m, indptr, perm, (const float4*)conv_b, agg0, aggh);
    gamma_both<<<blocks1 + blocks2, NTH>>>(aggh, row1, col1, s1a, E1, blocks1,
                                           row2, col2, s2a, E2);

    // ---- layer 1: conv GEMM with fused h-update + zero s1b|s2b ----
    gemm_k<2><<<GBM + SZB, NTH>>>(h, nullptr, wpk, m, nullptr, nullptr,
                                  agg0, skip, s1a, s2a, deg1, deg2, h,
                                  (float4*)s1b, nullptr, nullptr, nullptr, nullptr, 0,
                                  GBM, NN);
    scatter_sorted<<<scatB, NTH>>>(m, indptr, perm, (const float4*)(conv_b + HID), agg1, aggh);
    gamma_both<<<blocks1 + blocks2, NTH>>>(aggh, row1, col1, s1b, E1, blocks1,
                                           row2, col2, s2b, E2);

    // ---- output (layer-2 h-update fused) ----
    gemm_out_upd<<<(NN + ORPB - 1) / ORPB, dim3(40, ORPB)>>>(
        h, agg1, skip, s1b, s2b, deg1, deg2, fc_W, fc_b, out, NN);
}

// round 14
// speedup vs baseline: 1.1042x; 1.1042x over previous
#include <cuda_runtime.h>
#include <cuda_bf16.h>
#include <cuda_fp16.h>
#include <math.h>

#define NN 20000
#define HID 128
#define GBM 313         // GEMM blocks for 20000 rows @64/tile

// ---------------- single scratch buffer ----------------
#define OFF_H      0
#define OFF_M      2560000
#define OFF_SKIP   5120000
#define OFF_AGG0   7680000
#define OFF_AGG1   10240000
#define OFF_S1     12800000
#define OFF_S2     12820000
#define OFF_DEG    12840000   // deg1 | deg2 (float)
#define OFF_AGGH   12880000   // fp16 mirror of relu(agg): 1,280,000 floats
#define OFF_NRM    14160000   // n[v] = ||aggh_v||^2
#define OFF_WC1    14180000
#define OFF_WC2    14196384
#define OFF_WPK    14212768   // packed bf16 hi/lo weights (65,536)
#define OFF_CNTC   14278304   // int cntcol[NN]
#define OFF_IPC    14298304   // int indptrC[NN+1]
#define OFF_WOFFC  14318308   // int woffC[NN]
#define OFF_IP1    14338308   // int indptr1[NN+1]
#define OFF_WOFF1  14358312   // int woff1[NN]
#define OFF_IP2    14378312   // int indptr2[NN+1]
#define OFF_PERM   14398316   // int perm[<=130000]  (rows sorted by col)
#define OFF_PERMG  14528316   // int permg[<=130000] (cols sorted by row)
#define SCRATCH_F  14658316
__device__ float g_scratch[SCRATCH_F];

// ---------------- helpers ----------------
__device__ __forceinline__ float warp_red(float s) {
#pragma unroll
    for (int off = 16; off; off >>= 1) s += __shfl_xor_sync(0xffffffffu, s, off);
    return s;
}

__device__ __forceinline__ float4 relu4(float4 v) {
    return make_float4(fmaxf(v.x, 0.f), fmaxf(v.y, 0.f), fmaxf(v.z, 0.f), fmaxf(v.w, 0.f));
}

__device__ __forceinline__ float4 h4_to_f4(uint2 u) {
    __half2 a = *reinterpret_cast<__half2*>(&u.x);
    __half2 b = *reinterpret_cast<__half2*>(&u.y);
    float2 fa = __half22float2(a);
    float2 fb = __half22float2(b);
    return make_float4(fa.x, fa.y, fb.x, fb.y);
}

__device__ __forceinline__ void split_bf16(float f, unsigned short& h, unsigned short& l) {
    __nv_bfloat16 bh = __float2bfloat16_rn(f);
    float r = f - __bfloat162float(bh);
    __nv_bfloat16 bl = __float2bfloat16_rn(r);
    h = __bfloat16_as_ushort(bh);
    l = __bfloat16_as_ushort(bl);
}
__device__ __forceinline__ unsigned pack2(unsigned short lo_even, unsigned short hi_odd) {
    return ((unsigned)hi_odd << 16) | (unsigned)lo_even;
}

// ---------------- pre1: tiny fp32 GEMMs (blocks 0..15) + zero deg/cntcol tail ----------------
__global__ void pre1(const float* __restrict__ A,
                     const float* __restrict__ B1, const float* __restrict__ B2,
                     float* __restrict__ C1, float* __restrict__ C2,
                     float4* __restrict__ deg4, int4* __restrict__ cnt4) {
    int tid = threadIdx.x;
    if (blockIdx.x >= 16) {
        int i = (blockIdx.x - 16) * 256 + tid;
        if (i < 2 * NN / 4) deg4[i] = make_float4(0.f, 0.f, 0.f, 0.f);
        else if (i < 2 * NN / 4 + NN / 4) cnt4[i - 2 * NN / 4] = make_int4(0, 0, 0, 0);
        return;
    }
    int mat = blockIdx.x >> 3;
    int colBase = (blockIdx.x & 7) * 16;
    const float* B = mat ? B2 : B1;
    float* C = mat ? C2 : C1;
    __shared__ float As[16][129];
    __shared__ float Bs[16][16];
    int r = tid & 127;
    int cg = tid >> 7;
    float acc[8];
#pragma unroll
    for (int j = 0; j < 8; j++) acc[j] = 0.0f;
    for (int k0 = 0; k0 < 128; k0 += 16) {
        for (int i = tid; i < 128 * 16; i += 256) {
            int rr = i >> 4, kk = i & 15;
            As[kk][rr] = A[rr * 128 + k0 + kk];
        }
        {
            int kk = tid >> 4, cc = tid & 15;
            Bs[kk][cc] = B[(k0 + kk) * 128 + colBase + cc];
        }
        __syncthreads();
#pragma unroll
        for (int kk = 0; kk < 16; kk++) {
            float a = As[kk][r];
#pragma unroll
            for (int j = 0; j < 8; j++)
                acc[j] = fmaf(a, Bs[kk][cg * 8 + j], acc[j]);
        }
        __syncthreads();
    }
#pragma unroll
    for (int j = 0; j < 8; j++)
        C[r * 128 + colBase + cg * 8 + j] = acc[j];
}

// ---------------- pre2: prepack (blocks 0..127) + degree counts + col histogram ----------------
__global__ void pre2(const float* __restrict__ inW, const float* __restrict__ wc1,
                     const float* __restrict__ wc2, const float* __restrict__ convW1,
                     unsigned* __restrict__ wpk,
                     const int* __restrict__ row1, const int* __restrict__ col1, int E1,
                     const int* __restrict__ row2, int E2,
                     float* __restrict__ deg, int* __restrict__ cntcol) {
    int tid = threadIdx.x;
    if (blockIdx.x >= 128) {
        int e = (blockIdx.x - 128) * 256 + tid;
        if (e >= E1 + E2) return;
        int key = (e < E1) ? row1[e] : (NN + row2[e - E1]);
        unsigned m = __match_any_sync(__activemask(), key);
        if ((tid & 31) == (__ffs(m) - 1)) atomicAdd(&deg[key], (float)__popc(m));
        if (e < E1) atomicAdd(&cntcol[col1[e]], 1);
        return;
    }
    int idx = blockIdx.x * 256 + tid;
    int mat = idx >> 13;
    int rem = idx & 8191;
    int c = rem >> 10;
    int p = (rem >> 7) & 7;
    int n = rem & 127;
    const float* W = (mat == 0) ? inW : (mat == 1) ? wc1 : (mat == 2) ? wc2 : convW1;
    int k0 = c * 16 + 2 * p;
    float we = W[k0 * 128 + n];
    float wo = W[(k0 + 1) * 128 + n];
    unsigned short he, le, ho, lo_;
    split_bf16(we, he, le);
    split_bf16(wo, ho, lo_);
    wpk[mat * 16384 + rem] = pack2(he, ho);
    wpk[mat * 16384 + 8192 + rem] = pack2(le, lo_);
}

// ---------------- 3-way prefix scan (1 block each): cntcol, deg1, deg2 ----------------
__global__ __launch_bounds__(1024) void prefix3(const int* __restrict__ cntcol,
                                                const float* __restrict__ deg1,
                                                const float* __restrict__ deg2,
                                                int* __restrict__ ipC, int* __restrict__ woC,
                                                int* __restrict__ ip1, int* __restrict__ wo1,
                                                int* __restrict__ ip2) {
    __shared__ int ps[1024];
    const int CH = (NN + 1023) / 1024;   // 20
    int which = blockIdx.x;
    int t = threadIdx.x;
    int base = t * CH;
    int loc[CH];
    int s = 0;
#pragma unroll
    for (int j = 0; j < CH; j++) {
        int idx = base + j;
        int v = 0;
        if (idx < NN) {
            if (which == 0) v = cntcol[idx];
            else if (which == 1) v = (int)deg1[idx];
            else v = (int)deg2[idx];
        }
        loc[j] = s;
        s += v;
    }
    ps[t] = s;
    __syncthreads();
    for (int off = 1; off < 1024; off <<= 1) {
        int v = (t >= off) ? ps[t - off] : 0;
        __syncthreads();
        ps[t] += v;
        __syncthreads();
    }
    int excl = (t == 0) ? 0 : ps[t - 1];
    int* ip = (which == 0) ? ipC : (which == 1) ? ip1 : ip2;
    int* wo = (which == 0) ? woC : (which == 1) ? wo1 : nullptr;
#pragma unroll
    for (int j = 0; j < CH; j++) {
        int idx = base + j;
        if (idx < NN) {
            int val = excl + loc[j];
            ip[idx] = val;
            if (wo) wo[idx] = val;
        }
    }
    if (t == 1023) ip[NN] = ps[1023];
}

// ---------------- split-BF16 tensor GEMM, M=64 tile ----------------
// MODE 3: triple GEMM; tail: perm/permg build (E1 threads).
// MODE 2: fused h-update GEMM (no tail).
#define KCH 16
#define SPA 72
#define SPW 136
template<int MODE>
__global__ __launch_bounds__(256, 2) void gemm_k(
    const float* A, const float* __restrict__ A2, const unsigned* __restrict__ wpk,
    float* __restrict__ C, float* __restrict__ C2, float* __restrict__ C3,
    const float* __restrict__ agg, const float* __restrict__ skipb,
    const float* __restrict__ s1, const float* __restrict__ s2,
    const float* __restrict__ deg1, const float* __restrict__ deg2,
    float* hout,
    int* __restrict__ woffC, int* __restrict__ perm,
    int* __restrict__ woff1, int* __restrict__ permg,
    const int* __restrict__ prow, const int* __restrict__ pcol, int E1p,
    int gemmBlocks, int N) {
    const int tid = threadIdx.x;

    if ((int)blockIdx.x >= gemmBlocks) {
        int e = ((int)blockIdx.x - gemmBlocks) * 256 + tid;
        if (e < E1p) {
            int c = pcol[e];
            int r = prow[e];
            int pos = atomicAdd(&woffC[c], 1);
            perm[pos] = r;
            int pos2 = atomicAdd(&woff1[r], 1);
            permg[pos2] = c;
        }
        return;
    }

    __shared__ unsigned As_hi[8 * SPA], As_lo[8 * SPA];
    __shared__ unsigned Wv_hi[8 * SPW], Wv_lo[8 * SPW];
    __shared__ float cg1[64], cg2[64], cid[64];

    const int lane = tid & 31;
    const int warp = tid >> 5;
    const int g = lane >> 2;
    const int t = lane & 3;
    const int wm = warp & 3;
    const int wn = warp >> 2;
    const int mbase = wm * 16;
    const int nbase = wn * 64;

    const float* Ap = A;
    float* Cp = C;
    int mat, rb = blockIdx.x;
    if (MODE == 3) {
        if (rb < GBM) { mat = 0; }
        else if (rb < 2 * GBM) { mat = 1; Ap = A2; Cp = C2; rb -= GBM; }
        else { mat = 2; Cp = C3; rb -= 2 * GBM; }
    } else {
        mat = 3;
    }
    const int rowBase = rb * 64;
    const unsigned* Wh = wpk + mat * 16384;
    const unsigned* Wl = Wh + 8192;

    if (MODE == 2) {
        if (tid < 64) {
            int r = rowBase + tid;
            float G1 = 0.f, G2 = 0.f, ID = 1.f;
            if (r < N) {
                G1 = tanhf(s1[r] / (deg1[r] + 1e-10f));
                G2 = tanhf(s2[r] / (deg2[r] + 1e-10f));
                ID = 1.0f / (1.0f + G1 + G2);
            }
            cg1[tid] = G1; cg2[tid] = G2; cid[tid] = ID;
        }
        __syncthreads();
    }

    float acc[8][4];
#pragma unroll
    for (int n = 0; n < 8; n++)
#pragma unroll
        for (int j = 0; j < 4; j++) acc[n][j] = 0.0f;

    float4 pa;
    uint4 pwh, pwl;
    const int wp = tid >> 5;
    const int wnc = (tid & 31) * 4;

    auto loadA = [&](int k0) {
        int r = tid >> 2;
        int kq = (tid & 3) * 4;
        float4 v = make_float4(0.f, 0.f, 0.f, 0.f);
        if (rowBase + r < N) {
            size_t off = (size_t)(rowBase + r) * HID + k0 + kq;
            if (MODE == 2) {
                float4 h4 = *reinterpret_cast<const float4*>(&Ap[off]);
                float4 a4 = relu4(*reinterpret_cast<const float4*>(&agg[off]));
                float4 k4 = *reinterpret_cast<const float4*>(&skipb[off]);
                float G1 = cg1[r], G2 = cg2[r], ID = cid[r];
                v.x = (h4.x + G1 * a4.x + G2 * k4.x) * ID;
                v.y = (h4.y + G1 * a4.y + G2 * k4.y) * ID;
                v.z = (h4.z + G1 * a4.z + G2 * k4.z) * ID;
                v.w = (h4.w + G1 * a4.w + G2 * k4.w) * ID;
                *reinterpret_cast<float4*>(&hout[off]) = v;
            } else {
                v = *reinterpret_cast<const float4*>(&Ap[off]);
            }
        }
        pa = v;
    };
    auto loadW = [&](int c) {
        pwh = *reinterpret_cast<const uint4*>(&Wh[c * 1024 + wp * 128 + wnc]);
        pwl = *reinterpret_cast<const uint4*>(&Wl[c * 1024 + wp * 128 + wnc]);
    };

    loadA(0); loadW(0);

    for (int c = 0; c < 8; c++) {
        {
            int r = tid >> 2;
            int p0 = (tid & 3) * 2;
            float f[4] = {pa.x, pa.y, pa.z, pa.w};
            unsigned short h[4], l[4];
#pragma unroll
            for (int j = 0; j < 4; j++) split_bf16(f[j], h[j], l[j]);
            As_hi[p0 * SPA + r] = pack2(h[0], h[1]);
            As_lo[p0 * SPA + r] = pack2(l[0], l[1]);
            As_hi[(p0 + 1) * SPA + r] = pack2(h[2], h[3]);
            As_lo[(p0 + 1) * SPA + r] = pack2(l[2], l[3]);
        }
        *reinterpret_cast<uint4*>(&Wv_hi[wp * SPW + wnc]) = pwh;
        *reinterpret_cast<uint4*>(&Wv_lo[wp * SPW + wnc]) = pwl;
        __syncthreads();

        if (c + 1 < 8) { loadA((c + 1) * KCH); loadW(c + 1); }

        unsigned ah[4], al[4];
        ah[0] = As_hi[t * SPA + mbase + g];
        ah[1] = As_hi[t * SPA + mbase + g + 8];
        ah[2] = As_hi[(t + 4) * SPA + mbase + g];
        ah[3] = As_hi[(t + 4) * SPA + mbase + g + 8];
        al[0] = As_lo[t * SPA + mbase + g];
        al[1] = As_lo[t * SPA + mbase + g + 8];
        al[2] = As_lo[(t + 4) * SPA + mbase + g];
        al[3] = As_lo[(t + 4) * SPA + mbase + g + 8];
#pragma unroll
        for (int j = 0; j < 8; j++) {
            int n = nbase + j * 8 + g;
            unsigned bh0 = Wv_hi[t * SPW + n];
            unsigned bh1 = Wv_hi[(t + 4) * SPW + n];
            unsigned bl0 = Wv_lo[t * SPW + n];
            unsigned bl1 = Wv_lo[(t + 4) * SPW + n];
            asm volatile("mma.sync.aligned.m16n8k16.row.col.f32.bf16.bf16.f32 "
                         "{%0,%1,%2,%3}, {%4,%5,%6,%7}, {%8,%9}, {%0,%1,%2,%3};"
                         : "+f"(acc[j][0]), "+f"(acc[j][1]), "+f"(acc[j][2]), "+f"(acc[j][3])
                         : "r"(ah[0]), "r"(ah[1]), "r"(ah[2]), "r"(ah[3]), "r"(bh0), "r"(bh1));
            asm volatile("mma.sync.aligned.m16n8k16.row.col.f32.bf16.bf16.f32 "
                         "{%0,%1,%2,%3}, {%4,%5,%6,%7}, {%8,%9}, {%0,%1,%2,%3};"
                         : "+f"(acc[j][0]), "+f"(acc[j][1]), "+f"(acc[j][2]), "+f"(acc[j][3])
                         : "r"(ah[0]), "r"(ah[1]), "r"(ah[2]), "r"(ah[3]), "r"(bl0), "r"(bl1));
            asm volatile("mma.sync.aligned.m16n8k16.row.col.f32.bf16.bf16.f32 "
                         "{%0,%1,%2,%3}, {%4,%5,%6,%7}, {%8,%9}, {%0,%1,%2,%3};"
                         : "+f"(acc[j][0]), "+f"(acc[j][1]), "+f"(acc[j][2]), "+f"(acc[j][3])
                         : "r"(al[0]), "r"(al[1]), "r"(al[2]), "r"(al[3]), "r"(bh0), "r"(bh1));
        }
        __syncthreads();
    }

    int r0 = rowBase + mbase + g;
    int r1 = r0 + 8;
    if (r0 < N) {
#pragma unroll
        for (int j = 0; j < 8; j++)
            *reinterpret_cast<float2*>(&Cp[(size_t)r0 * HID + nbase + j * 8 + 2 * t]) =
                make_float2(acc[j][0], acc[j][1]);
    }
    if (r1 < N) {
#pragma unroll
        for (int j = 0; j < 8; j++)
            *reinterpret_cast<float2*>(&Cp[(size_t)r1 * HID + nbase + j * 8 + 2 * t]) =
                make_float2(acc[j][2], acc[j][3]);
    }
}

// ---------------- sorted scatter + fp16 mirror + per-node norm ----------------
__global__ void scatter_sorted(const float* __restrict__ m, const int* __restrict__ indptr,
                               const int* __restrict__ perm, const float4* __restrict__ bias4,
                               float* __restrict__ agg, uint2* __restrict__ aggh,
                               float* __restrict__ nrm) {
    int w = (blockIdx.x * blockDim.x + threadIdx.x) >> 5;
    if (w >= NN) return;
    int lane = threadIdx.x & 31;
    int beg = indptr[w], end = indptr[w + 1];
    float4 acc = bias4[lane];
    int e = beg;
    for (; e + 4 <= end; e += 4) {
        int r0 = perm[e], r1 = perm[e + 1], r2 = perm[e + 2], r3 = perm[e + 3];
        float4 v0 = *reinterpret_cast<const float4*>(&m[(size_t)r0 * HID + lane * 4]);
        float4 v1 = *reinterpret_cast<const float4*>(&m[(size_t)r1 * HID + lane * 4]);
        float4 v2 = *reinterpret_cast<const float4*>(&m[(size_t)r2 * HID + lane * 4]);
        float4 v3 = *reinterpret_cast<const float4*>(&m[(size_t)r3 * HID + lane * 4]);
        acc.x += v0.x + v1.x + v2.x + v3.x;
        acc.y += v0.y + v1.y + v2.y + v3.y;
        acc.z += v0.z + v1.z + v2.z + v3.z;
        acc.w += v0.w + v1.w + v2.w + v3.w;
    }
    for (; e < end; e++) {
        int r = perm[e];
        float4 v = *reinterpret_cast<const float4*>(&m[(size_t)r * HID + lane * 4]);
        acc.x += v.x; acc.y += v.y; acc.z += v.z; acc.w += v.w;
    }
    *reinterpret_cast<float4*>(&agg[(size_t)w * HID + lane * 4]) = acc;
    __half2 a = __float22half2_rn(make_float2(fmaxf(acc.x, 0.f), fmaxf(acc.y, 0.f)));
    __half2 b = __float22half2_rn(make_float2(fmaxf(acc.z, 0.f), fmaxf(acc.w, 0.f)));
    uint2 o;
    o.x = *reinterpret_cast<unsigned*>(&a);
    o.y = *reinterpret_cast<unsigned*>(&b);
    aggh[(size_t)w * 32 + lane] = o;
    // per-node norm of the fp16-rounded values (consistent with gamma's gathers)
    float2 fa = __half22float2(a);
    float2 fb = __half22float2(b);
    float nl = fa.x * fa.x + fa.y * fa.y + fb.x * fb.x + fb.y * fb.y;
    float nv = warp_red(nl);
    if (lane == 0) nrm[w] = nv;
}

// ---------------- gamma via norm identity, CSR per node, no atomics ----------------
// s[r] = deg_r * n_r + sum_c n_c - 2 * a_r . (sum_c a_c)
__global__ void gamma_csr(const uint2* __restrict__ aggh, const float* __restrict__ nrm,
                          const int* __restrict__ ip1, const int* __restrict__ cols1,
                          const int* __restrict__ ip2, const int* __restrict__ cols2,
                          float* __restrict__ s1, float* __restrict__ s2) {
    int w = (blockIdx.x * blockDim.x + threadIdx.x) >> 5;
    int lane = threadIdx.x & 31;
    if (w >= 2 * NN) return;
    const int* ip;
    const int* cols;
    float* sOut;
    int r;
    if (w < NN) { r = w; ip = ip1; cols = cols1; sOut = s1; }
    else { r = w - NN; ip = ip2; cols = cols2; sOut = s2; }
    int beg = ip[r], end = ip[r + 1];
    float4 ar = h4_to_f4(aggh[(size_t)r * 32 + lane]);
    float4 S = make_float4(0.f, 0.f, 0.f, 0.f);
    float nsum = 0.f;
    int e = beg;
    for (; e + 4 <= end; e += 4) {
        int c0 = cols[e], c1 = cols[e + 1], c2 = cols[e + 2], c3 = cols[e + 3];
        uint2 u0 = aggh[(size_t)c0 * 32 + lane];
        uint2 u1 = aggh[(size_t)c1 * 32 + lane];
        uint2 u2 = aggh[(size_t)c2 * 32 + lane];
        uint2 u3 = aggh[(size_t)c3 * 32 + lane];
        nsum += nrm[c0] + nrm[c1] + nrm[c2] + nrm[c3];
        float4 a0 = h4_to_f4(u0), a1 = h4_to_f4(u1);
        float4 a2 = h4_to_f4(u2), a3 = h4_to_f4(u3);
        S.x += a0.x + a1.x + a2.x + a3.x;
        S.y += a0.y + a1.y + a2.y + a3.y;
        S.z += a0.z + a1.z + a2.z + a3.z;
        S.w += a0.w + a1.w + a2.w + a3.w;
    }
    for (; e < end; e++) {
        int c = cols[e];
        uint2 u = aggh[(size_t)c * 32 + lane];
        nsum += nrm[c];
        float4 a = h4_to_f4(u);
        S.x += a.x; S.y += a.y; S.z += a.z; S.w += a.w;
    }
    float dot = ar.x * S.x + ar.y * S.y + ar.z * S.z + ar.w * S.w;
    dot = warp_red(dot);
    if (lane == 0)
        sOut[r] = (float)(end - beg) * nrm[r] + nsum - 2.0f * dot;
}

// ---------------- final GEMM with fused layer-2 h-update ----------------
#define ORPB 16
__global__ __launch_bounds__(640) void gemm_out_upd(
    const float* __restrict__ h, const float* __restrict__ agg, const float* __restrict__ skip,
    const float* __restrict__ s1, const float* __restrict__ s2,
    const float* __restrict__ deg1, const float* __restrict__ deg2,
    const float* __restrict__ W, const float* __restrict__ bias,
    float* __restrict__ C, int N) {
    __shared__ float Ws[HID * 41];
    __shared__ float bs[40];
    __shared__ float As[ORPB][HID];
    __shared__ float cg1[ORPB], cg2[ORPB], cid[ORPB];
    int tid = threadIdx.y * 40 + threadIdx.x;
    int rowBase = blockIdx.x * ORPB;

    for (int i = tid; i < HID * 40; i += 640) {
        int k = i / 40, n = i % 40;
        Ws[k * 41 + n] = W[i];
    }
    if (tid < 40) bs[tid] = bias[tid];
    if (tid < ORPB) {
        int r = rowBase + tid;
        float g1 = 0.f, g2 = 0.f, invd = 1.f;
        if (r < N) {
            g1 = tanhf(s1[r] / (deg1[r] + 1e-10f));
            g2 = tanhf(s2[r] / (deg2[r] + 1e-10f));
            invd = 1.0f / (1.0f + g1 + g2);
        }
        cg1[tid] = g1; cg2[tid] = g2; cid[tid] = invd;
    }
    __syncthreads();

    for (int i = tid; i < ORPB * HID; i += 640) {
        int rr = i >> 7, kk = i & (HID - 1);
        int r = rowBase + rr;
        float v = 0.0f;
        if (r < N) {
            size_t off = (size_t)r * HID + kk;
            v = (h[off] + cg1[rr] * fmaxf(agg[off], 0.f) + cg2[rr] * skip[off]) * cid[rr];
        }
        As[rr][kk] = v;
    }
    __syncthreads();

    int row = rowBase + threadIdx.y;
    if (row >= N) return;
    float acc = bs[threadIdx.x];
#pragma unroll
    for (int k = 0; k < HID; k++) acc = fmaf(As[threadIdx.y][k], Ws[k * 41 + threadIdx.x], acc);
    C[(size_t)row * 40 + threadIdx.x] = acc;
}

// ---------------- launcher ----------------
extern "C" void kernel_launch(void* const* d_in, const int* in_sizes, int n_in,
                              void* d_out, int out_size) {
    const float* x       = (const float*)d_in[0];
    const float* x0      = (const float*)d_in[1];
    const int*   ei      = (const int*)d_in[2];
    const int*   ei2     = (const int*)d_in[3];
    const float* in_W    = (const float*)d_in[4];
    const float* skip_W  = (const float*)d_in[5];
    const float* conv_W  = (const float*)d_in[6];
    const float* conv_b  = (const float*)d_in[7];
    const float* fc_W    = (const float*)d_in[8];
    const float* fc_b    = (const float*)d_in[9];
    float* out = (float*)d_out;

    const int E1 = in_sizes[2] / 2;
    const int E2 = in_sizes[3] / 2;
    const int* row1 = ei;
    const int* col1 = ei + E1;
    const int* row2 = ei2;
    const int* col2 = ei2 + E2;

    float* base;
    cudaGetSymbolAddress((void**)&base, g_scratch);
    float* h    = base + OFF_H;
    float* m    = base + OFF_M;
    float* skip = base + OFF_SKIP;
    float* agg0 = base + OFF_AGG0;
    float* agg1 = base + OFF_AGG1;
    float* s1   = base + OFF_S1;
    float* s2   = base + OFF_S2;
    float* deg1 = base + OFF_DEG;
    float* deg2 = deg1 + NN;
    uint2* aggh = (uint2*)(base + OFF_AGGH);
    float* nrm  = base + OFF_NRM;
    float* wc1  = base + OFF_WC1;
    float* wc2  = base + OFF_WC2;
    unsigned* wpk = (unsigned*)(base + OFF_WPK);
    int* cntcol = (int*)(base + OFF_CNTC);
    int* ipC    = (int*)(base + OFF_IPC);
    int* woC    = (int*)(base + OFF_WOFFC);
    int* ip1    = (int*)(base + OFF_IP1);
    int* wo1    = (int*)(base + OFF_WOFF1);
    int* ip2    = (int*)(base + OFF_IP2);
    int* perm   = (int*)(base + OFF_PERM);
    int* permg  = (int*)(base + OFF_PERMG);

    const int NTH = 256;
    const int zeroB   = (2 * NN / 4 + NN / 4 + NTH - 1) / NTH;   // deg + cntcol
    const int countB  = (E1 + E2 + NTH - 1) / NTH;
    const int permB   = (E1 + NTH - 1) / NTH;
    const int scatB   = (NN * 32 + NTH - 1) / NTH;
    const int gamB    = (2 * NN * 32 + NTH - 1) / NTH;

    // pre1: Wc1/Wc2 tiny GEMMs + zero deg/cntcol
    pre1<<<16 + zeroB, NTH>>>(in_W, skip_W, conv_W, wc1, wc2,
                              (float4*)deg1, (int4*)cntcol);
    // pre2: weight prepack + row-degree counts + col histogram
    pre2<<<128 + countB, NTH>>>(in_W, wc1, wc2, conv_W + (size_t)HID * HID, wpk,
                                row1, col1, E1, row2, E2, deg1, cntcol);
    // 3-way prefix scan
    prefix3<<<3, 1024>>>(cntcol, deg1, deg2, ipC, woC, ip1, wo1, ip2);

    // triple GEMM (h = x@in_W ; skip = x0@Wc1 ; m = x@Wc2) + perm/permg build
    gemm_k<3><<<3 * GBM + permB, NTH>>>(x, x0, wpk, h, skip, m,
                                        nullptr, nullptr, nullptr, nullptr,
                                        nullptr, nullptr, nullptr,
                                        woC, perm, wo1, permg, row1, col1, E1,
                                        3 * GBM, NN);

    // ---- layer 0 ----
    scatter_sorted<<<scatB, NTH>>>(m, ipC, perm, (const float4*)conv_b, agg0, aggh, nrm);
    gamma_csr<<<gamB, NTH>>>(aggh, nrm, ip1, permg, ip2, col2, s1, s2);

    // ---- layer 1: conv GEMM with fused h-update ----
    gemm_k<2><<<GBM, NTH>>>(h, nullptr, wpk, m, nullptr, nullptr,
                            agg0, skip, s1, s2, deg1, deg2, h,
                            nullptr, nullptr, nullptr, nullptr, nullptr, nullptr, 0,
                            GBM, NN);
    scatter_sorted<<<scatB, NTH>>>(m, ipC, perm, (const float4*)(conv_b + HID), agg1, aggh, nrm);
    gamma_csr<<<gamB, NTH>>>(aggh, nrm, ip1, permg, ip2, col2, s1, s2);

    // ---- output (layer-2 h-update fused) ----
    gemm_out_upd<<<(NN + ORPB - 1) / ORPB, dim3(40, ORPB)>>>(
        h, agg1, skip, s1, s2, deg1, deg2, fc_W, fc_b, out, NN);
}